// round 8
// baseline (speedup 1.0000x reference)
#include <cuda_runtime.h>
#include <cstdint>
#include <math.h>

#define B 96
#define N 512
#define M 512
#define D 32

#define THREADS 256          // warp 0 = DTW consumer, warps 1..7 = cost producers
#define RSLOTS 40            // ring: 32-row consumption window + 8 lead
#define SLOT_F 640           // 32 * 20 floats (16 data + 4 pad) per row slot
#define TSTRIDE_F 20
#define S2STR 36             // staged seq2 row stride in floats (144B, bank-spread)

#define OFF_S2    0                          // 512*36            = 18432 floats
#define OFF_RING  (512 * S2STR)              // 40*640            = 25600 floats
#define OFF_SQ2   (OFF_RING + RSLOTS * SLOT_F)   // 512 floats
#define OFF_FLAGS (OFF_SQ2 + 512)            // 512 ints
#define OFF_PROG  (OFF_FLAGS + 512)
#define SMEM_FLOATS (OFF_PROG + 4)
#define SMEM_BYTES (SMEM_FLOATS * 4)         // 180240 B

// ---------------------------------------------------------------------------
// helpers
// ---------------------------------------------------------------------------
__device__ __forceinline__ unsigned long long pack2f(float x, float y) {
    unsigned long long r;
    asm("mov.b64 %0, {%1, %2};" : "=l"(r) : "f"(x), "f"(y));
    return r;
}
__device__ __forceinline__ void ffma2(unsigned long long& d,
                                      unsigned long long a, unsigned long long b) {
    asm("fma.rn.f32x2 %0, %1, %2, %0;" : "+l"(d) : "l"(a), "l"(b));
}
__device__ __forceinline__ void unpack2f(unsigned long long v, float& x, float& y) {
    asm("mov.b64 {%0, %1}, %2;" : "=f"(x), "=f"(y) : "l"(v));
}
__device__ __forceinline__ void lds_v2u64(unsigned saddr,
                                          unsigned long long& a, unsigned long long& b) {
    asm volatile("ld.shared.v2.u64 {%0, %1}, [%2];" : "=l"(a), "=l"(b) : "r"(saddr));
}
__device__ __forceinline__ void sts_f32(unsigned saddr, float v) {
    asm volatile("st.shared.f32 [%0], %1;" :: "r"(saddr), "f"(v) : "memory");
}
__device__ __forceinline__ float fast_sqrt(float x) {
    float r;
    asm("sqrt.approx.f32 %0, %1;" : "=f"(r) : "f"(x));
    return r;
}
__device__ __forceinline__ void cp_async16(unsigned dst, const float* src) {
    asm volatile("cp.async.cg.shared.global [%0], [%1], 16;\n"
                 :: "r"(dst), "l"(src) : "memory");
}
__device__ __forceinline__ int ld_acquire_s32(unsigned addr) {
    int v;
    asm volatile("ld.acquire.cta.shared.b32 %0, [%1];" : "=r"(v) : "r"(addr) : "memory");
    return v;
}
__device__ __forceinline__ void st_release_s32(unsigned addr, int v) {
    asm volatile("st.release.cta.shared.b32 [%0], %1;" :: "r"(addr), "r"(v) : "memory");
}

// ---------------------------------------------------------------------------
// Fused kernel: 1 CTA per batch. Producers (warps 1-7) compute cost rows
// FFMA2-style into a 40-slot smem ring; consumer (warp 0) runs the skewed
// DTW wavefront with the min-plus prefix restructure.
// ---------------------------------------------------------------------------
__global__ __launch_bounds__(THREADS)
void fused_dtw(const float* __restrict__ seq1, const float* __restrict__ seq2,
               float* __restrict__ out)
{
    extern __shared__ float sm[];
    const int b = blockIdx.x;
    const int tid = threadIdx.x;
    const int wid = tid >> 5;
    const int lane = tid & 31;

    const unsigned smb   = (unsigned)__cvta_generic_to_shared(sm);
    const unsigned s2b   = smb + OFF_S2 * 4;
    const unsigned ringb = smb + OFF_RING * 4;
    const unsigned flagb = smb + OFF_FLAGS * 4;
    volatile int* prog = (volatile int*)(sm + OFF_PROG);

    // ---- stage seq2 (padded 144B rows), init flags, compute sq2 ----
    const float* s2g = seq2 + (size_t)b * M * D;
    for (int c = tid; c < 512 * 8; c += THREADS) {
        int row = c >> 3, q = c & 7;
        cp_async16(s2b + (unsigned)(row * S2STR * 4 + q * 16), s2g + row * 32 + q * 4);
    }
    asm volatile("cp.async.commit_group;\n" ::: "memory");
    for (int i = tid; i < 512; i += THREADS) ((int*)(sm + OFF_FLAGS))[i] = 0;
    if (tid == 0) *prog = -1;
    asm volatile("cp.async.wait_group 0;\n" ::: "memory");
    __syncthreads();
    for (int jj = tid; jj < 512; jj += THREADS) {
        const float* rp = sm + OFF_S2 + jj * S2STR;
        float acc = 0.f;
#pragma unroll
        for (int k = 0; k < 32; ++k) acc = fmaf(rp[k], rp[k], acc);
        sm[OFF_SQ2 + jj] = acc;
    }
    __syncthreads();

    if (wid == 0) {
        // =================== CONSUMER: DTW wavefront ===================
        const int t = lane;
        const float INF = INFINITY;

        float vprev[16];
#pragma unroll
        for (int k = 0; k < 16; ++k) vprev[k] = INF;
        float diag0 = (t == 0) ? 0.f : INF;
        float lastv = INF;

        const int STEPS = N + 31;   // 543

        for (int s = 0; s < STEPS; ++s) {
            float left0 = __shfl_up_sync(0xffffffffu, lastv, 1);
            if (t == 0) left0 = INF;

            if (s < N) {
                // row s must be ready before any lane touches it this step
                if (ld_acquire_s32(flagb + (unsigned)s * 4) == 0) {
                    while (ld_acquire_s32(flagb + (unsigned)s * 4) == 0) __nanosleep(32);
                }
            }

            const int r = s - t;
            if (r >= 0 && r < N) {
                const float4* cp = reinterpret_cast<const float4*>(
                    sm + OFF_RING + (r % RSLOTS) * SLOT_F + t * TSTRIDE_F);
                float4 c0 = cp[0], c1 = cp[1], c2 = cp[2], c3 = cp[3];
                float c[16] = { c0.x, c0.y, c0.z, c0.w,
                                c1.x, c1.y, c1.z, c1.w,
                                c2.x, c2.y, c2.z, c2.w,
                                c3.x, c3.y, c3.z, c3.w };

                float P[16];
                P[0] = c[0];
#pragma unroll
                for (int k = 1; k < 16; ++k) P[k] = P[k - 1] + c[k];

                float w[16];
                {
                    float m0 = fminf(vprev[0], diag0);
                    w[0] = m0;                      // P[-1] = 0
#pragma unroll
                    for (int k = 1; k < 16; ++k) {
                        float mk = fminf(vprev[k], vprev[k - 1]);
                        w[k] = mk - P[k - 1];
                    }
                }
#pragma unroll
                for (int k = 1; k < 16; ++k) w[k] = fminf(w[k], w[k - 1]);
#pragma unroll
                for (int k = 0; k < 16; ++k)
                    vprev[k] = P[k] + fminf(left0, w[k]);

                lastv = vprev[15];
                diag0 = left0;
            }

            if (lane == 0) *prog = s;   // step s fully consumed
        }

        if (t == 31) out[b] = lastv;
    } else {
        // =================== PRODUCERS: cost rows ===================
        const int base = wid - 1;       // 0..6
        const float* s1g = seq1 + (size_t)b * N * D;

        for (int r1 = base; r1 < N; r1 += 14) {
            const int r2 = r1 + 7;
            const bool has2 = (r2 < N);
            const int rmax = has2 ? r2 : r1;

            if (rmax >= RSLOTS) {
                while (*prog < rmax - 8) __nanosleep(64);
            }
            __syncwarp();

            // load s1 rows (uniform across lanes -> broadcast), pack f32x2
            unsigned long long p1[16], p2[16];
            float sq1a = 0.f, sq1b = 0.f;
            {
                const float4* v = reinterpret_cast<const float4*>(s1g + (size_t)r1 * D);
#pragma unroll
                for (int q = 0; q < 8; ++q) {
                    float4 x = v[q];
                    p1[2 * q] = pack2f(x.x, x.y); p1[2 * q + 1] = pack2f(x.z, x.w);
                    sq1a = fmaf(x.x, x.x, sq1a); sq1a = fmaf(x.y, x.y, sq1a);
                    sq1a = fmaf(x.z, x.z, sq1a); sq1a = fmaf(x.w, x.w, sq1a);
                }
            }
            if (has2) {
                const float4* v = reinterpret_cast<const float4*>(s1g + (size_t)r2 * D);
#pragma unroll
                for (int q = 0; q < 8; ++q) {
                    float4 x = v[q];
                    p2[2 * q] = pack2f(x.x, x.y); p2[2 * q + 1] = pack2f(x.z, x.w);
                    sq1b = fmaf(x.x, x.x, sq1b); sq1b = fmaf(x.y, x.y, sq1b);
                    sq1b = fmaf(x.z, x.z, sq1b); sq1b = fmaf(x.w, x.w, sq1b);
                }
            }

            const unsigned slot1 = ringb + (unsigned)((r1 % RSLOTS) * SLOT_F * 4);
            const unsigned slot2 = ringb + (unsigned)((r2 % RSLOTS) * SLOT_F * 4);

#pragma unroll 1
            for (int i = 0; i < 16; ++i) {
                const int j = lane + 32 * i;       // bank-spread: lane stride 144B
                const unsigned aaddr = s2b + (unsigned)(j * S2STR * 4);

                unsigned long long a0, a1, a2, a3, a4, a5, a6, a7;
                unsigned long long x0 = 0ull, x1 = 0ull, y0 = 0ull, y1 = 0ull;

                lds_v2u64(aaddr +  0, a0, a1);
                lds_v2u64(aaddr + 16, a2, a3);
                lds_v2u64(aaddr + 32, a4, a5);
                lds_v2u64(aaddr + 48, a6, a7);
                ffma2(x0, a0, p1[0]); ffma2(x1, a1, p1[1]);
                ffma2(x0, a2, p1[2]); ffma2(x1, a3, p1[3]);
                ffma2(x0, a4, p1[4]); ffma2(x1, a5, p1[5]);
                ffma2(x0, a6, p1[6]); ffma2(x1, a7, p1[7]);
                if (has2) {
                    ffma2(y0, a0, p2[0]); ffma2(y1, a1, p2[1]);
                    ffma2(y0, a2, p2[2]); ffma2(y1, a3, p2[3]);
                    ffma2(y0, a4, p2[4]); ffma2(y1, a5, p2[5]);
                    ffma2(y0, a6, p2[6]); ffma2(y1, a7, p2[7]);
                }
                lds_v2u64(aaddr + 64, a0, a1);
                lds_v2u64(aaddr + 80, a2, a3);
                lds_v2u64(aaddr + 96, a4, a5);
                lds_v2u64(aaddr + 112, a6, a7);
                ffma2(x0, a0, p1[8]);  ffma2(x1, a1, p1[9]);
                ffma2(x0, a2, p1[10]); ffma2(x1, a3, p1[11]);
                ffma2(x0, a4, p1[12]); ffma2(x1, a5, p1[13]);
                ffma2(x0, a6, p1[14]); ffma2(x1, a7, p1[15]);
                if (has2) {
                    ffma2(y0, a0, p2[8]);  ffma2(y1, a1, p2[9]);
                    ffma2(y0, a2, p2[10]); ffma2(y1, a3, p2[11]);
                    ffma2(y0, a4, p2[12]); ffma2(y1, a5, p2[13]);
                    ffma2(y0, a6, p2[14]); ffma2(y1, a7, p2[15]);
                }

                const float sq2j = sm[OFF_SQ2 + j];
                const unsigned off = (unsigned)(((2 * i + (lane >> 4)) * TSTRIDE_F
                                                 + (lane & 15)) * 4);
                {
                    float e0, e1, e2, e3;
                    unpack2f(x0, e0, e1); unpack2f(x1, e2, e3);
                    float dot = (e0 + e1) + (e2 + e3);
                    float dd = sq1a + sq2j - 2.f * dot;
                    sts_f32(slot1 + off, fast_sqrt(fmaxf(dd, 1e-12f)));
                }
                if (has2) {
                    float e0, e1, e2, e3;
                    unpack2f(y0, e0, e1); unpack2f(y1, e2, e3);
                    float dot = (e0 + e1) + (e2 + e3);
                    float dd = sq1b + sq2j - 2.f * dot;
                    sts_f32(slot2 + off, fast_sqrt(fmaxf(dd, 1e-12f)));
                }
            }

            __syncwarp();
            if (lane == 0) {
                st_release_s32(flagb + (unsigned)r1 * 4, 1);
                if (has2) st_release_s32(flagb + (unsigned)r2 * 4, 1);
            }
        }
    }
}

// ---------------------------------------------------------------------------
extern "C" void kernel_launch(void* const* d_in, const int* in_sizes, int n_in,
                              void* d_out, int out_size)
{
    const float* seq1 = (const float*)d_in[0];
    const float* seq2 = (const float*)d_in[1];
    float* out = (float*)d_out;

    cudaFuncSetAttribute(fused_dtw, cudaFuncAttributeMaxDynamicSharedMemorySize,
                         SMEM_BYTES);
    fused_dtw<<<B, THREADS, SMEM_BYTES>>>(seq1, seq2, out);
}

// round 9
// speedup vs baseline: 7.0247x; 7.0247x over previous
#include <cuda_runtime.h>
#include <cstdint>
#include <math.h>

#define B 96
#define N 512
#define M 512
#define D 32

#define THREADS 256          // warps 0..6 = cost producers, warp 7 = DTW consumer
#define RSLOTS 52            // ring: 32-row consumption window + 20-row lead
#define LEAD   (RSLOTS - 32) // 20
#define SLOT_F 640           // 32 * 20 floats (16 data + 4 pad) per row slot
#define TSTRIDE_F 20
#define S2STR 36             // staged seq2 row stride in floats (144B, bank-spread)

#define OFF_S2    0                              // 512*36  = 18432 floats
#define OFF_RING  (512 * S2STR)                  // 52*640  = 33280 floats
#define OFF_SQ2   (OFF_RING + RSLOTS * SLOT_F)   // 512 floats
#define OFF_FLAGS (OFF_SQ2 + 512)                // 512 ints
#define OFF_PROG  (OFF_FLAGS + 512)
#define SMEM_FLOATS (OFF_PROG + 4)
#define SMEM_BYTES (SMEM_FLOATS * 4)             // 210,960 B (< 227KB cap)

// ---------------------------------------------------------------------------
// helpers
// ---------------------------------------------------------------------------
__device__ __forceinline__ unsigned long long pack2f(float x, float y) {
    unsigned long long r;
    asm("mov.b64 %0, {%1, %2};" : "=l"(r) : "f"(x), "f"(y));
    return r;
}
__device__ __forceinline__ void ffma2(unsigned long long& d,
                                      unsigned long long a, unsigned long long b) {
    asm("fma.rn.f32x2 %0, %1, %2, %0;" : "+l"(d) : "l"(a), "l"(b));
}
__device__ __forceinline__ void unpack2f(unsigned long long v, float& x, float& y) {
    asm("mov.b64 {%0, %1}, %2;" : "=f"(x), "=f"(y) : "l"(v));
}
__device__ __forceinline__ void lds_v2u64(unsigned saddr,
                                          unsigned long long& a, unsigned long long& b) {
    asm volatile("ld.shared.v2.u64 {%0, %1}, [%2];" : "=l"(a), "=l"(b) : "r"(saddr));
}
__device__ __forceinline__ void sts_f32(unsigned saddr, float v) {
    asm volatile("st.shared.f32 [%0], %1;" :: "r"(saddr), "f"(v) : "memory");
}
__device__ __forceinline__ float fast_sqrt(float x) {
    float r;
    asm("sqrt.approx.f32 %0, %1;" : "=f"(r) : "f"(x));
    return r;
}
__device__ __forceinline__ void cp_async16(unsigned dst, const float* src) {
    asm volatile("cp.async.cg.shared.global [%0], [%1], 16;\n"
                 :: "r"(dst), "l"(src) : "memory");
}
__device__ __forceinline__ int ld_acquire_s32(unsigned addr) {
    int v;
    asm volatile("ld.acquire.cta.shared.b32 %0, [%1];" : "=r"(v) : "r"(addr) : "memory");
    return v;
}
__device__ __forceinline__ void st_release_s32(unsigned addr, int v) {
    asm volatile("st.release.cta.shared.b32 [%0], %1;" :: "r"(addr), "r"(v) : "memory");
}

// ---------------------------------------------------------------------------
// Fused kernel: 1 CTA per batch. Producers (warps 0-6) compute ADJACENT row
// pairs (r, r+1) FFMA2-style into a 52-slot smem ring (20-row lead);
// consumer (warp 7, hi-wid arbiter priority) runs the skewed DTW wavefront.
// ---------------------------------------------------------------------------
__global__ __launch_bounds__(THREADS)
void fused_dtw(const float* __restrict__ seq1, const float* __restrict__ seq2,
               float* __restrict__ out)
{
    extern __shared__ float sm[];
    const int b = blockIdx.x;
    const int tid = threadIdx.x;
    const int wid = tid >> 5;
    const int lane = tid & 31;

    const unsigned smb   = (unsigned)__cvta_generic_to_shared(sm);
    const unsigned s2b   = smb + OFF_S2 * 4;
    const unsigned ringb = smb + OFF_RING * 4;
    const unsigned flagb = smb + OFF_FLAGS * 4;
    const unsigned progb = smb + OFF_PROG * 4;

    // ---- stage seq2 (padded 144B rows), init flags, compute sq2 ----
    const float* s2g = seq2 + (size_t)b * M * D;
    for (int c = tid; c < 512 * 8; c += THREADS) {
        int row = c >> 3, q = c & 7;
        cp_async16(s2b + (unsigned)(row * S2STR * 4 + q * 16), s2g + row * 32 + q * 4);
    }
    asm volatile("cp.async.commit_group;\n" ::: "memory");
    for (int i = tid; i < 512; i += THREADS) ((int*)(sm + OFF_FLAGS))[i] = 0;
    if (tid == 0) ((int*)(sm + OFF_PROG))[0] = -1;
    asm volatile("cp.async.wait_group 0;\n" ::: "memory");
    __syncthreads();
    for (int jj = tid; jj < 512; jj += THREADS) {
        const float* rp = sm + OFF_S2 + jj * S2STR;
        float acc = 0.f;
#pragma unroll
        for (int k = 0; k < 32; ++k) acc = fmaf(rp[k], rp[k], acc);
        sm[OFF_SQ2 + jj] = acc;
    }
    __syncthreads();

    if (wid == 7) {
        // =================== CONSUMER: DTW wavefront ===================
        const int t = lane;
        const float INF = INFINITY;

        float vprev[16];
#pragma unroll
        for (int k = 0; k < 16; ++k) vprev[k] = INF;
        float diag0 = (t == 0) ? 0.f : INF;
        float lastv = INF;

        const int STEPS = N + 31;   // 543

        for (int s = 0; s < STEPS; ++s) {
            float left0 = __shfl_up_sync(0xffffffffu, lastv, 1);
            if (t == 0) left0 = INF;

            if (s < N) {
                if (ld_acquire_s32(flagb + (unsigned)s * 4) == 0) {
                    while (ld_acquire_s32(flagb + (unsigned)s * 4) == 0) __nanosleep(20);
                }
            }

            const int r = s - t;
            if (r >= 0 && r < N) {
                const float4* cp = reinterpret_cast<const float4*>(
                    sm + OFF_RING + (r % RSLOTS) * SLOT_F + t * TSTRIDE_F);
                float4 c0 = cp[0], c1 = cp[1], c2 = cp[2], c3 = cp[3];
                float c[16] = { c0.x, c0.y, c0.z, c0.w,
                                c1.x, c1.y, c1.z, c1.w,
                                c2.x, c2.y, c2.z, c2.w,
                                c3.x, c3.y, c3.z, c3.w };

                float P[16];
                P[0] = c[0];
#pragma unroll
                for (int k = 1; k < 16; ++k) P[k] = P[k - 1] + c[k];

                float w[16];
                {
                    float m0 = fminf(vprev[0], diag0);
                    w[0] = m0;                      // P[-1] = 0
#pragma unroll
                    for (int k = 1; k < 16; ++k) {
                        float mk = fminf(vprev[k], vprev[k - 1]);
                        w[k] = mk - P[k - 1];
                    }
                }
#pragma unroll
                for (int k = 1; k < 16; ++k) w[k] = fminf(w[k], w[k - 1]);
#pragma unroll
                for (int k = 0; k < 16; ++k)
                    vprev[k] = P[k] + fminf(left0, w[k]);

                lastv = vprev[15];
                diag0 = left0;
            }

            if (lane == 0) st_release_s32(progb, s);   // step s fully consumed
        }

        if (t == 31) out[b] = lastv;
    } else {
        // =================== PRODUCERS: adjacent cost-row pairs ===================
        const float* s1g = seq1 + (size_t)b * N * D;

        for (int r1 = 2 * wid; r1 < N; r1 += 14) {
            const int r2 = r1 + 1;                 // always < N (r1 even, N=512)

            if (r2 >= RSLOTS) {                    // ring-reuse gate: 20-row lead
                if (ld_acquire_s32(progb) < r2 - LEAD) {
                    while (ld_acquire_s32(progb) < r2 - LEAD) __nanosleep(40);
                }
            }
            __syncwarp();

            // load s1 rows (uniform across lanes -> broadcast), pack f32x2
            unsigned long long p1[16], p2[16];
            float sq1a = 0.f, sq1b = 0.f;
            {
                const float4* v = reinterpret_cast<const float4*>(s1g + (size_t)r1 * D);
#pragma unroll
                for (int q = 0; q < 8; ++q) {
                    float4 x = v[q];
                    p1[2 * q] = pack2f(x.x, x.y); p1[2 * q + 1] = pack2f(x.z, x.w);
                    sq1a = fmaf(x.x, x.x, sq1a); sq1a = fmaf(x.y, x.y, sq1a);
                    sq1a = fmaf(x.z, x.z, sq1a); sq1a = fmaf(x.w, x.w, sq1a);
                }
            }
            {
                const float4* v = reinterpret_cast<const float4*>(s1g + (size_t)r2 * D);
#pragma unroll
                for (int q = 0; q < 8; ++q) {
                    float4 x = v[q];
                    p2[2 * q] = pack2f(x.x, x.y); p2[2 * q + 1] = pack2f(x.z, x.w);
                    sq1b = fmaf(x.x, x.x, sq1b); sq1b = fmaf(x.y, x.y, sq1b);
                    sq1b = fmaf(x.z, x.z, sq1b); sq1b = fmaf(x.w, x.w, sq1b);
                }
            }

            const unsigned slot1 = ringb + (unsigned)((r1 % RSLOTS) * SLOT_F * 4);
            const unsigned slot2 = ringb + (unsigned)((r2 % RSLOTS) * SLOT_F * 4);

#pragma unroll 1
            for (int i = 0; i < 16; ++i) {
                const int j = lane + 32 * i;       // bank-spread: lane stride 144B
                const unsigned aaddr = s2b + (unsigned)(j * S2STR * 4);

                unsigned long long a0, a1, a2, a3, a4, a5, a6, a7;
                unsigned long long x0 = 0ull, x1 = 0ull, y0 = 0ull, y1 = 0ull;

                lds_v2u64(aaddr +  0, a0, a1);
                lds_v2u64(aaddr + 16, a2, a3);
                lds_v2u64(aaddr + 32, a4, a5);
                lds_v2u64(aaddr + 48, a6, a7);
                ffma2(x0, a0, p1[0]); ffma2(x1, a1, p1[1]);
                ffma2(x0, a2, p1[2]); ffma2(x1, a3, p1[3]);
                ffma2(x0, a4, p1[4]); ffma2(x1, a5, p1[5]);
                ffma2(x0, a6, p1[6]); ffma2(x1, a7, p1[7]);
                ffma2(y0, a0, p2[0]); ffma2(y1, a1, p2[1]);
                ffma2(y0, a2, p2[2]); ffma2(y1, a3, p2[3]);
                ffma2(y0, a4, p2[4]); ffma2(y1, a5, p2[5]);
                ffma2(y0, a6, p2[6]); ffma2(y1, a7, p2[7]);

                lds_v2u64(aaddr + 64, a0, a1);
                lds_v2u64(aaddr + 80, a2, a3);
                lds_v2u64(aaddr + 96, a4, a5);
                lds_v2u64(aaddr + 112, a6, a7);
                ffma2(x0, a0, p1[8]);  ffma2(x1, a1, p1[9]);
                ffma2(x0, a2, p1[10]); ffma2(x1, a3, p1[11]);
                ffma2(x0, a4, p1[12]); ffma2(x1, a5, p1[13]);
                ffma2(x0, a6, p1[14]); ffma2(x1, a7, p1[15]);
                ffma2(y0, a0, p2[8]);  ffma2(y1, a1, p2[9]);
                ffma2(y0, a2, p2[10]); ffma2(y1, a3, p2[11]);
                ffma2(y0, a4, p2[12]); ffma2(y1, a5, p2[13]);
                ffma2(y0, a6, p2[14]); ffma2(y1, a7, p2[15]);

                const float sq2j = sm[OFF_SQ2 + j];
                const unsigned off = (unsigned)(((2 * i + (lane >> 4)) * TSTRIDE_F
                                                 + (lane & 15)) * 4);
                {
                    float e0, e1, e2, e3;
                    unpack2f(x0, e0, e1); unpack2f(x1, e2, e3);
                    float dot = (e0 + e1) + (e2 + e3);
                    float dd = sq1a + sq2j - 2.f * dot;
                    sts_f32(slot1 + off, fast_sqrt(fmaxf(dd, 1e-12f)));
                }
                {
                    float e0, e1, e2, e3;
                    unpack2f(y0, e0, e1); unpack2f(y1, e2, e3);
                    float dot = (e0 + e1) + (e2 + e3);
                    float dd = sq1b + sq2j - 2.f * dot;
                    sts_f32(slot2 + off, fast_sqrt(fmaxf(dd, 1e-12f)));
                }
            }

            __syncwarp();
            if (lane == 0) {
                st_release_s32(flagb + (unsigned)r1 * 4, 1);
                st_release_s32(flagb + (unsigned)r2 * 4, 1);
            }
        }
    }
}

// ---------------------------------------------------------------------------
extern "C" void kernel_launch(void* const* d_in, const int* in_sizes, int n_in,
                              void* d_out, int out_size)
{
    const float* seq1 = (const float*)d_in[0];
    const float* seq2 = (const float*)d_in[1];
    float* out = (float*)d_out;

    cudaFuncSetAttribute(fused_dtw, cudaFuncAttributeMaxDynamicSharedMemorySize,
                         SMEM_BYTES);
    fused_dtw<<<B, THREADS, SMEM_BYTES>>>(seq1, seq2, out);
}